// round 1
// baseline (speedup 1.0000x reference)
#include <cuda_runtime.h>
#include <math.h>

#define NTS      4096
#define SEQ_LEN  168
#define HORIZON  24
#define TTOT     (SEQ_LEN + HORIZON)
#define F_IN     32
#define EMBED    32
#define HIDDEN   64
#define LAYERS   2

// smem layout sizes (floats)
#define SW_FLOATS   (2 * 192 * 64)   // 2 layers x (i,g,o = 192 rows) x 64
#define SB_FLOATS   (2 * 192)
#define SMALL_FLOATS (32 + 32 + 64 + 64)
#define SMEM_A_FLOATS (SW_FLOATS + SB_FLOATS + SMALL_FLOATS)
#define SMEM_B_FLOATS (SW_FLOATS + SB_FLOATS + SMALL_FLOATS + 8 * 64)

__device__ __forceinline__ float sigm(float x) { return 1.0f / (1.0f + expf(-x)); }
__device__ __forceinline__ float tanh_(float x) { return tanhf(x); }
__device__ __forceinline__ float softplus_(float x) {
    return (x > 20.0f) ? x : log1pf(expf(x));
}

// gate row remap: smem row r in [0,192): i rows 0..63 -> src 0..63,
// g rows 64..127 -> src 128..191, o rows 128..191 -> src 192..255
__device__ __forceinline__ int src_row(int r) { return r + ((r >= 64) ? 64 : 0); }

// ---------------------------------------------------------------------------
// Phase A: all teacher-forced steps t in [0, SEQ_LEN). One thread = one (n,t).
// Weights in smem, row-major [192][64] per layer; all threads in a warp read
// the same address -> broadcast, conflict free, 4 FMAs per LDS.128.
// ---------------------------------------------------------------------------
__global__ void __launch_bounds__(256, 2) deepar_phaseA(
    const float* __restrict__ X, const float* __restrict__ y,
    const float* __restrict__ W_embed, const float* __restrict__ b_embed,
    const float* __restrict__ W_ih, const float* __restrict__ b_ih,
    const float* __restrict__ b_hh,
    const float* __restrict__ W_mu, const float* __restrict__ b_mu,
    const float* __restrict__ W_sigma, const float* __restrict__ b_sigma,
    float* __restrict__ out)
{
    extern __shared__ float sm[];
    float* sW   = sm;                 // [2][192][64]
    float* sB   = sW + SW_FLOATS;     // [2][192]
    float* sWe  = sB + SB_FLOATS;     // [32]
    float* sBe  = sWe + 32;           // [32]
    float* sWmu = sBe + 32;           // [64]
    float* sWsg = sWmu + 64;          // [64]

    const int tid = threadIdx.x;
    for (int idx = tid; idx < SW_FLOATS; idx += blockDim.x) {
        int l = idx / 12288, rem = idx % 12288;
        int r = rem / 64, k = rem % 64;
        sW[idx] = W_ih[l * 16384 + src_row(r) * 64 + k];
    }
    for (int idx = tid; idx < SB_FLOATS; idx += blockDim.x) {
        int l = idx / 192, r = idx % 192;
        int sr = l * 256 + src_row(r);
        sB[idx] = b_ih[sr] + b_hh[sr];
    }
    if (tid < 32) { sWe[tid] = W_embed[tid]; sBe[tid] = b_embed[tid]; }
    if (tid < 64) { sWmu[tid] = W_mu[tid]; sWsg[tid] = W_sigma[tid]; }
    __syncthreads();

    const int item = blockIdx.x * blockDim.x + tid;
    if (item >= NTS * SEQ_LEN) return;
    const int n = item / SEQ_LEN;
    const int t = item % SEQ_LEN;

    float h[64];
    const float4* xp = (const float4*)(X + (size_t)item * F_IN);
    #pragma unroll
    for (int q = 0; q < 8; ++q) {
        float4 v = xp[q];
        h[4 * q + 0] = v.x; h[4 * q + 1] = v.y;
        h[4 * q + 2] = v.z; h[4 * q + 3] = v.w;
    }
    const float yn = y[item];
    #pragma unroll
    for (int e = 0; e < 32; ++e) h[32 + e] = fmaf(yn, sWe[e], sBe[e]);

    float hn[64];
    #pragma unroll
    for (int l = 0; l < LAYERS; ++l) {
        const float* W = sW + l * 12288;
        const float* B = sB + l * 192;
        for (int j = 0; j < 64; ++j) {
            float ai = B[j], ag = B[64 + j], ao = B[128 + j];
            const float* wi = W + j * 64;
            const float* wg = W + (64 + j) * 64;
            const float* wo = W + (128 + j) * 64;
            #pragma unroll
            for (int k = 0; k < 64; ++k) {
                ai = fmaf(wi[k], h[k], ai);
                ag = fmaf(wg[k], h[k], ag);
                ao = fmaf(wo[k], h[k], ao);
            }
            float c = sigm(ai) * tanh_(ag);
            hn[j] = sigm(ao) * tanh_(c);
        }
        #pragma unroll
        for (int k = 0; k < 64; ++k) h[k] = hn[k];
    }

    float mu = b_mu[0], sl = b_sigma[0];
    #pragma unroll
    for (int k = 0; k < 64; ++k) {
        float r = fmaxf(h[k], 0.0f);
        mu = fmaf(r, sWmu[k], mu);
        sl = fmaf(r, sWsg[k], sl);
    }
    float sigma = softplus_(sl) + 1e-6f;

    float* out_mu = out + NTS * HORIZON;
    float* out_sg = out_mu + NTS * TTOT;
    out_mu[n * TTOT + t] = mu;
    out_sg[n * TTOT + t] = sigma;

    if (t == SEQ_LEN - 1) {
        float s2 = sigma * sigma;
        float d = yn - mu;
        float lik = rsqrtf(2.0f * (float)M_PI * s2) * expf(-(d * d) / (2.0f * s2));
        out[n * HORIZON + 0] = lik;  // ypred[:,0] = lik at t=167; also the carry seed
    }
}

// ---------------------------------------------------------------------------
// Phase B: 24 sequential horizon steps, one warp per series.
// Weights in smem TRANSPOSED per layer: WT[k][192] so that lane-indexed row
// reads are conflict-free. h lives in per-warp smem (64 floats).
// ---------------------------------------------------------------------------
__global__ void __launch_bounds__(256, 2) deepar_phaseB(
    const float* __restrict__ Xf,
    const float* __restrict__ W_embed, const float* __restrict__ b_embed,
    const float* __restrict__ W_ih, const float* __restrict__ b_ih,
    const float* __restrict__ b_hh,
    const float* __restrict__ W_mu, const float* __restrict__ b_mu,
    const float* __restrict__ W_sigma, const float* __restrict__ b_sigma,
    float* __restrict__ out)
{
    extern __shared__ float sm[];
    float* sWT  = sm;                 // [2][64][192]: WT[l][k*192 + row]
    float* sB   = sWT + SW_FLOATS;
    float* sWe  = sB + SB_FLOATS;
    float* sBe  = sWe + 32;
    float* sWmu = sBe + 32;
    float* sWsg = sWmu + 64;
    float* sH   = sWsg + 64;          // [8 warps][64]

    const int tid = threadIdx.x;
    for (int idx = tid; idx < SW_FLOATS; idx += blockDim.x) {
        int l = idx / 12288, rem = idx % 12288;
        int r = rem / 64, k = rem % 64;
        sWT[l * 12288 + k * 192 + r] = W_ih[l * 16384 + src_row(r) * 64 + k];
    }
    for (int idx = tid; idx < SB_FLOATS; idx += blockDim.x) {
        int l = idx / 192, r = idx % 192;
        int sr = l * 256 + src_row(r);
        sB[idx] = b_ih[sr] + b_hh[sr];
    }
    if (tid < 32) { sWe[tid] = W_embed[tid]; sBe[tid] = b_embed[tid]; }
    if (tid < 64) { sWmu[tid] = W_mu[tid]; sWsg[tid] = W_sigma[tid]; }
    __syncthreads();

    const int lane = tid & 31;
    const int wl   = tid >> 5;
    const int n    = blockIdx.x * (blockDim.x >> 5) + wl;
    if (n >= NTS) return;

    float* sh = sH + wl * 64;
    float* out_mu = out + NTS * HORIZON;
    float* out_sg = out_mu + NTS * TTOT;
    const float bmu = b_mu[0], bsg = b_sigma[0];
    const float we = sWe[lane], be = sBe[lane];
    const float wmu0 = sWmu[lane], wmu1 = sWmu[32 + lane];
    const float wsg0 = sWsg[lane], wsg1 = sWsg[32 + lane];

    float carry = out[n * HORIZON + 0];  // lik at t = SEQ_LEN-1, written by phase A

    for (int step = 0; step < HORIZON; ++step) {
        const int t = SEQ_LEN + step;
        const float yn = carry;
        sh[lane]      = Xf[((size_t)n * HORIZON + step) * F_IN + lane];
        sh[32 + lane] = fmaf(yn, we, be);
        __syncwarp();

        #pragma unroll
        for (int l = 0; l < LAYERS; ++l) {
            const float* WT = sWT + l * 12288;
            const float* B  = sB + l * 192;
            float a0 = B[lane],      a1 = B[64 + lane],      a2 = B[128 + lane];
            float a3 = B[32 + lane], a4 = B[96 + lane],      a5 = B[160 + lane];
            #pragma unroll
            for (int k = 0; k < 64; ++k) {
                const float hk = sh[k];
                const float* row = WT + k * 192;
                a0 = fmaf(row[lane],       hk, a0);
                a1 = fmaf(row[64 + lane],  hk, a1);
                a2 = fmaf(row[128 + lane], hk, a2);
                a3 = fmaf(row[32 + lane],  hk, a3);
                a4 = fmaf(row[96 + lane],  hk, a4);
                a5 = fmaf(row[160 + lane], hk, a5);
            }
            float c0 = sigm(a0) * tanh_(a1);
            float h0 = sigm(a2) * tanh_(c0);
            float c1 = sigm(a3) * tanh_(a4);
            float h1 = sigm(a5) * tanh_(c1);
            __syncwarp();
            sh[lane] = h0; sh[32 + lane] = h1;
            __syncwarp();
        }

        float r0 = fmaxf(sh[lane], 0.0f), r1 = fmaxf(sh[32 + lane], 0.0f);
        float pm = r0 * wmu0 + r1 * wmu1;
        float ps = r0 * wsg0 + r1 * wsg1;
        #pragma unroll
        for (int off = 16; off; off >>= 1) {
            pm += __shfl_xor_sync(0xFFFFFFFFu, pm, off);
            ps += __shfl_xor_sync(0xFFFFFFFFu, ps, off);
        }
        float mu = pm + bmu;
        float sigma = softplus_(ps + bsg) + 1e-6f;
        float s2 = sigma * sigma;
        float d = yn - mu;
        float lik = rsqrtf(2.0f * (float)M_PI * s2) * expf(-(d * d) / (2.0f * s2));

        if (lane == 0) {
            out_mu[n * TTOT + t] = mu;
            out_sg[n * TTOT + t] = sigma;
            if (t <= SEQ_LEN + HORIZON - 2)
                out[n * HORIZON + (t - (SEQ_LEN - 1))] = lik;
        }
        carry = lik;
    }
}

extern "C" void kernel_launch(void* const* d_in, const int* in_sizes, int n_in,
                              void* d_out, int out_size)
{
    const float* X       = (const float*)d_in[0];
    const float* y       = (const float*)d_in[1];
    const float* Xf      = (const float*)d_in[2];
    const float* W_embed = (const float*)d_in[3];
    const float* b_embed = (const float*)d_in[4];
    const float* W_ih    = (const float*)d_in[5];
    const float* b_ih    = (const float*)d_in[6];
    const float* b_hh    = (const float*)d_in[7];
    const float* W_mu    = (const float*)d_in[8];
    const float* b_mu    = (const float*)d_in[9];
    const float* W_sigma = (const float*)d_in[10];
    const float* b_sigma = (const float*)d_in[11];
    float* out = (float*)d_out;

    static bool attr_done = false;
    if (!attr_done) {
        cudaFuncSetAttribute(deepar_phaseA,
            cudaFuncAttributeMaxDynamicSharedMemorySize, SMEM_A_FLOATS * 4);
        cudaFuncSetAttribute(deepar_phaseB,
            cudaFuncAttributeMaxDynamicSharedMemorySize, SMEM_B_FLOATS * 4);
        attr_done = true;
    }

    const int itemsA = NTS * SEQ_LEN;
    const int blkA = 256;
    deepar_phaseA<<<(itemsA + blkA - 1) / blkA, blkA, SMEM_A_FLOATS * 4>>>(
        X, y, W_embed, b_embed, W_ih, b_ih, b_hh, W_mu, b_mu, W_sigma, b_sigma, out);

    const int blkB = 256;                 // 8 warps/block, 1 warp per series
    const int gridB = (NTS * 32 + blkB - 1) / blkB;
    deepar_phaseB<<<gridB, blkB, SMEM_B_FLOATS * 4>>>(
        Xf, W_embed, b_embed, W_ih, b_ih, b_hh, W_mu, b_mu, W_sigma, b_sigma, out);
}